// round 10
// baseline (speedup 1.0000x reference)
#include <cuda_runtime.h>
#include <math.h>

// S4D real SSM, v5: single fused kernel with deterministic in-kernel group
// scan (no decoupled lookback):
//   phase 1: every block computes its chunk aggregate, bumps group counter
//   scan:    the group's chunk-0 block scans all 32 chunk prefixes (L2-hot,
//            full MLP, no polling chain), sets done flag
//   phase 3: all blocks load h0 once and run the output recurrence
// All 512 blocks co-resident (256 thr, <=64 regs, 32KB smem, 4 blocks/SM).

#define LEN 4096
#define CH  512
#define S   64
#define NC  32
#define LC  128
#define CS  (CH*S)
#define DT  (1.0/4096.0)

#define NPK 4              // f32x2 pairs per lane (8 states)
#define SPL 8              // states per lane
#define CPW 4              // channels per warp
#define CPB 32             // channels per block
#define NG  (CH/CPB)       // 16 channel groups

typedef unsigned long long ull;

__device__ float g_a [CS];      // exp(A*dt)
__device__ float g_cb[CS];      // C * Bd
__device__ float g_dc[CS];      // exp(A*dt*LC) (chunk decay)
__device__ float g_v [NC*CS];   // chunk aggregates
__device__ float g_h0[NC*CS];   // per-chunk initial states (scan output)
__device__ int   g_cnt [NG];    // aggregates published per group
__device__ int   g_done[NG];    // group scan complete

// ---- packed f32x2 helpers (Blackwell FFMA2, PTX-only) ---------------------
__device__ __forceinline__ ull pack2(float x, float y) {
    ull r; asm("mov.b64 %0, {%1, %2};" : "=l"(r) : "f"(x), "f"(y)); return r;
}
__device__ __forceinline__ ull fma2(ull a, ull b, ull c) {
    ull d; asm("fma.rn.f32x2 %0, %1, %2, %3;" : "=l"(d) : "l"(a), "l"(b), "l"(c)); return d;
}
__device__ __forceinline__ ull mul2(ull a, ull b) {
    ull d; asm("mul.rn.f32x2 %0, %1, %2;" : "=l"(d) : "l"(a), "l"(b)); return d;
}
__device__ __forceinline__ float hsum2(ull v) {
    float lo, hi; asm("mov.b64 {%0, %1}, %2;" : "=f"(lo), "=f"(hi) : "l"(v));
    return lo + hi;
}
__device__ __forceinline__ int ld_acq(const int* p) {
    int v; asm volatile("ld.acquire.gpu.global.b32 %0, [%1];" : "=r"(v) : "l"(p) : "memory");
    return v;
}
__device__ __forceinline__ void st_rel(int* p, int v) {
    asm volatile("st.release.gpu.global.b32 [%0], %1;" :: "l"(p), "r"(v) : "memory");
}

// ---------------------------------------------------------------- precompute
// also resets the sync state for each graph replay (same-stream ordering)
__global__ void precompute_k(const float* __restrict__ lognegA,
                             const float* __restrict__ B,
                             const float* __restrict__ C)
{
    int i = blockIdx.x * blockDim.x + threadIdx.x;
    if (i < NG) { g_cnt[i] = 0; g_done[i] = 0; }
    if (i >= CS) return;
    double A  = -exp((double)lognegA[i]);
    double ad = A * DT;
    double Bd = expm1(ad) / A * (double)B[i];
    g_a [i] = (float)exp(ad);
    g_cb[i] = (float)((double)C[i] * Bd);
    g_dc[i] = (float)exp(ad * (double)LC);
}

// ---------------------------------------------------------------- fused
__global__ __launch_bounds__(256, 4)
void fused_k(const float* __restrict__ x, float* __restrict__ y)
{
    __shared__ ull sx[LC][CPB];          // packed {x,x} tile, 32 KB
    const int k     = blockIdx.x;        // chunk
    const int gb    = blockIdx.y;        // channel group
    const int cbase = gb * CPB;
    const int tid   = threadIdx.x;
    const int w     = tid >> 5;
    const int lane  = tid & 31;
    const int g     = lane >> 3;         // channel within warp
    const int q     = lane & 7;          // lane within 8-lane channel team
    const int l0    = k * LC;

    // ---- tile load: float4 from gmem, duplicated into packed ull smem
    #pragma unroll 4
    for (int i = tid; i < LC * CPB / 4; i += 256) {
        int lr = i >> 3, c4 = (i & 7) << 2;
        float4 v4 = *reinterpret_cast<const float4*>(x + (l0 + lr) * CH + cbase + c4);
        sx[lr][c4 + 0] = pack2(v4.x, v4.x);
        sx[lr][c4 + 1] = pack2(v4.y, v4.y);
        sx[lr][c4 + 2] = pack2(v4.z, v4.z);
        sx[lr][c4 + 3] = pack2(v4.w, v4.w);
    }
    __syncthreads();

    const int c     = cbase + w * CPW + g;
    const int sbase = c * S + q * SPL;
    const int chl   = w * CPW + g;

    ull a[NPK];
    const ull* aP = reinterpret_cast<const ull*>(g_a + sbase);
    #pragma unroll
    for (int t = 0; t < NPK; t++) a[t] = aP[t];

    // ---- phase 1: chunk aggregate (zero initial state)
    ull v[NPK] = {0ull, 0ull, 0ull, 0ull};
    #pragma unroll 8
    for (int l = 0; l < LC; l++) {
        ull xx = sx[l][chl];
        #pragma unroll
        for (int t = 0; t < NPK; t++) v[t] = fma2(a[t], v[t], xx);
    }
    {   // publish aggregate, bump group counter (release)
        ull* vP = reinterpret_cast<ull*>(g_v + k * CS + sbase);
        #pragma unroll
        for (int t = 0; t < NPK; t++) vP[t] = v[t];
        __threadfence();
        __syncthreads();
        if (tid == 0) atomicAdd(&g_cnt[gb], 1);
    }

    // ---- group scan: chunk-0 block computes h0 for all chunks of its group
    if (k == 0) {
        if (tid == 0) {
            while (ld_acq(&g_cnt[gb]) != NC) __nanosleep(32);
        }
        __syncthreads();
        const int sb = cbase * S;        // 2048 states = 1024 ulls
        #pragma unroll
        for (int u = tid; u < CPB * S / 2; u += 256) {      // 4 ulls / thread
            ull d2 = reinterpret_cast<const ull*>(g_dc + sb)[u];
            ull h  = 0ull;
            #pragma unroll 8
            for (int kk = 0; kk < NC; kk++) {
                if (kk) reinterpret_cast<ull*>(g_h0 + kk * CS + sb)[u] = h;
                ull vv = __ldcg(reinterpret_cast<const ull*>(g_v + kk * CS + sb) + u);
                h = fma2(d2, h, vv);
            }
        }
        __syncthreads();
        if (tid == 0) st_rel(&g_done[gb], 1);
    }

    // ---- wait for group scan, load h0
    if (tid == 0) {
        while (ld_acq(&g_done[gb]) == 0) __nanosleep(32);
    }
    __syncthreads();

    ull h[NPK];
    if (k == 0) {
        #pragma unroll
        for (int t = 0; t < NPK; t++) h[t] = 0ull;
    } else {
        const ull* hP = reinterpret_cast<const ull*>(g_h0 + k * CS + sbase);
        #pragma unroll
        for (int t = 0; t < NPK; t++) h[t] = __ldcg(hP + t);
    }

    // ---- phase 3: output recurrence from h0
    ull cb[NPK];
    const ull* cbP = reinterpret_cast<const ull*>(g_cb + sbase);
    #pragma unroll
    for (int t = 0; t < NPK; t++) cb[t] = cbP[t];

    #pragma unroll 2
    for (int r = 0; r < LC / 8; r++) {
        float p[8];
        #pragma unroll
        for (int j = 0; j < 8; j++) {
            ull xx = sx[r * 8 + j][chl];
            #pragma unroll
            for (int t = 0; t < NPK; t++) h[t] = fma2(a[t], h[t], xx);
            ull acc = mul2(cb[0], h[0]);
            #pragma unroll
            for (int t = 1; t < NPK; t++) acc = fma2(cb[t], h[t], acc);
            p[j] = hsum2(acc);
        }
        // 3-stage register-halving butterfly over the 8-lane team:
        // afterwards lane q holds the finished output for step r*8+q
        #pragma unroll
        for (int d = 4; d >= 1; d >>= 1) {
            #pragma unroll
            for (int m = 0; m < d; m++) {
                bool  hi   = (q & d) != 0;
                float send = hi ? p[m] : p[m + d];
                float got  = __shfl_xor_sync(0xffffffffu, send, d);
                p[m] = (hi ? p[m + d] : p[m]) + got;
            }
        }
        y[(l0 + r * 8 + q) * CH + c] = p[0];
    }
}

// ---------------------------------------------------------------- launch
extern "C" void kernel_launch(void* const* d_in, const int* in_sizes, int n_in,
                              void* d_out, int out_size)
{
    const float* x       = (const float*)d_in[0];
    const float* lognegA = (const float*)d_in[1];
    const float* B       = (const float*)d_in[2];
    const float* C       = (const float*)d_in[3];
    float*       y       = (float*)d_out;

    precompute_k<<<CS / 256, 256>>>(lognegA, B, C);   // also resets sync state
    dim3 grid(NC, NG);
    fused_k<<<grid, 256>>>(x, y);
}

// round 12
// speedup vs baseline: 1.5854x; 1.5854x over previous
#include <cuda_runtime.h>
#include <math.h>

// S4D real SSM, v6: fused kernel, aggregates-only cross-chunk combine.
//   phase 1: each block computes its chunk aggregate v_k, publishes it
//            (stores + threadfence + release flag). NO prefixes, NO chain.
//   wait:    warp-parallel poll: lane j watches predecessor j's flag.
//   combine: h0(k) = sum_{j<k} D^(k-1-j) * v_j  -- independent L2-hot loads,
//            MLP-friendly, ~O(k) packed fma2 per lane.
//   phase 3: output recurrence from h0.
// 512 blocks of 256 thr, 4 blocks/SM, all co-resident in one wave.

#define LEN 4096
#define CH  512
#define S   64
#define NC  32
#define LC  128
#define CS  (CH*S)
#define DT  (1.0/4096.0)

#define NPK 4              // f32x2 pairs per lane (8 states)
#define SPL 8              // states per lane
#define CPW 4              // channels per warp
#define CPB 32             // channels per block
#define NG  (CH/CPB)       // 16 channel groups

typedef unsigned long long ull;

__device__ float g_a [CS];      // exp(A*dt)
__device__ float g_cb[CS];      // C * Bd
__device__ float g_dc[CS];      // exp(A*dt*LC) (chunk decay)
__device__ float g_v [NC*CS];   // chunk aggregates
__device__ int   g_flag[NC*NG]; // aggregate published (0/1); [j*NG+gb]

// ---- packed f32x2 helpers (Blackwell FFMA2, PTX-only) ---------------------
__device__ __forceinline__ ull pack2(float x, float y) {
    ull r; asm("mov.b64 %0, {%1, %2};" : "=l"(r) : "f"(x), "f"(y)); return r;
}
__device__ __forceinline__ ull fma2(ull a, ull b, ull c) {
    ull d; asm("fma.rn.f32x2 %0, %1, %2, %3;" : "=l"(d) : "l"(a), "l"(b), "l"(c)); return d;
}
__device__ __forceinline__ ull mul2(ull a, ull b) {
    ull d; asm("mul.rn.f32x2 %0, %1, %2;" : "=l"(d) : "l"(a), "l"(b)); return d;
}
__device__ __forceinline__ float hsum2(ull v) {
    float lo, hi; asm("mov.b64 {%0, %1}, %2;" : "=f"(lo), "=f"(hi) : "l"(v));
    return lo + hi;
}
__device__ __forceinline__ int ld_rlx(const int* p) {
    int v; asm volatile("ld.relaxed.gpu.global.b32 %0, [%1];" : "=r"(v) : "l"(p) : "memory");
    return v;
}
__device__ __forceinline__ void st_rel(int* p, int v) {
    asm volatile("st.release.gpu.global.b32 [%0], %1;" :: "l"(p), "r"(v) : "memory");
}

// ---------------------------------------------------------------- precompute
// also resets flags each graph replay (same-stream ordering before fused_k)
__global__ void precompute_k(const float* __restrict__ lognegA,
                             const float* __restrict__ B,
                             const float* __restrict__ C)
{
    int i = blockIdx.x * blockDim.x + threadIdx.x;
    if (i < NC * NG) g_flag[i] = 0;
    if (i >= CS) return;
    double A  = -exp((double)lognegA[i]);
    double ad = A * DT;
    double Bd = expm1(ad) / A * (double)B[i];
    g_a [i] = (float)exp(ad);
    g_cb[i] = (float)((double)C[i] * Bd);
    g_dc[i] = (float)exp(ad * (double)LC);
}

// ---------------------------------------------------------------- fused
__global__ __launch_bounds__(256, 4)
void fused_k(const float* __restrict__ x, float* __restrict__ y)
{
    __shared__ ull sx[LC][CPB];          // packed {x,x} tile, 32 KB
    const int k     = blockIdx.x;        // chunk
    const int gb    = blockIdx.y;        // channel group
    const int cbase = gb * CPB;
    const int tid   = threadIdx.x;
    const int w     = tid >> 5;
    const int lane  = tid & 31;
    const int g     = lane >> 3;         // channel within warp
    const int q     = lane & 7;          // lane within 8-lane channel team
    const int l0    = k * LC;

    // ---- tile load: float4 from gmem, duplicated into packed ull smem
    #pragma unroll 4
    for (int i = tid; i < LC * CPB / 4; i += 256) {
        int lr = i >> 3, c4 = (i & 7) << 2;
        float4 v4 = *reinterpret_cast<const float4*>(x + (l0 + lr) * CH + cbase + c4);
        sx[lr][c4 + 0] = pack2(v4.x, v4.x);
        sx[lr][c4 + 1] = pack2(v4.y, v4.y);
        sx[lr][c4 + 2] = pack2(v4.z, v4.z);
        sx[lr][c4 + 3] = pack2(v4.w, v4.w);
    }
    __syncthreads();

    const int c     = cbase + w * CPW + g;
    const int sbase = c * S + q * SPL;
    const int chl   = w * CPW + g;

    ull a[NPK];
    const ull* aP = reinterpret_cast<const ull*>(g_a + sbase);
    #pragma unroll
    for (int t = 0; t < NPK; t++) a[t] = aP[t];

    // ---- phase 1: chunk aggregate (zero initial state)
    ull v[NPK] = {0ull, 0ull, 0ull, 0ull};
    #pragma unroll 8
    for (int l = 0; l < LC; l++) {
        ull xx = sx[l][chl];
        #pragma unroll
        for (int t = 0; t < NPK; t++) v[t] = fma2(a[t], v[t], xx);
    }

    // ---- publish aggregate (all chunks; chunk 0's v is needed by everyone)
    if (k < NC - 1 || true) {
        ull* vP = reinterpret_cast<ull*>(g_v + k * CS + sbase);
        #pragma unroll
        for (int t = 0; t < NPK; t++) vP[t] = v[t];
        __threadfence();
        __syncthreads();
        if (tid == 0) st_rel(&g_flag[k * NG + gb], 1);
    }

    // ---- wait (warp-parallel) + combine: h0 = sum_{j<k} D^(k-1-j) v_j
    ull h[NPK] = {0ull, 0ull, 0ull, 0ull};
    if (k > 0) {
        // lane j polls predecessor j's flag; flags are 64B apart per j
        const int* fp = (lane < k) ? &g_flag[lane * NG + gb] : (const int*)0;
        while (true) {
            int f = fp ? ld_rlx(fp) : 1;
            if (__all_sync(0xffffffffu, f != 0)) break;
            __nanosleep(64);
        }
        __threadfence();                 // acquire: order v reads after flags

        ull dc[NPK], dpow[NPK];
        const ull* dP = reinterpret_cast<const ull*>(g_dc + sbase);
        const ull one = pack2(1.f, 1.f);
        #pragma unroll
        for (int t = 0; t < NPK; t++) { dc[t] = dP[t]; dpow[t] = one; }

        #pragma unroll 4
        for (int j = k - 1; j >= 0; j--) {
            const ull* vj = reinterpret_cast<const ull*>(g_v + j * CS + sbase);
            ull l0v = __ldcg(vj + 0), l1v = __ldcg(vj + 1);
            ull l2v = __ldcg(vj + 2), l3v = __ldcg(vj + 3);
            h[0] = fma2(dpow[0], l0v, h[0]);
            h[1] = fma2(dpow[1], l1v, h[1]);
            h[2] = fma2(dpow[2], l2v, h[2]);
            h[3] = fma2(dpow[3], l3v, h[3]);
            #pragma unroll
            for (int t = 0; t < NPK; t++) dpow[t] = mul2(dpow[t], dc[t]);
        }
    }

    // ---- phase 3: output recurrence from h0
    ull cb[NPK];
    const ull* cbP = reinterpret_cast<const ull*>(g_cb + sbase);
    #pragma unroll
    for (int t = 0; t < NPK; t++) cb[t] = cbP[t];

    #pragma unroll 2
    for (int r = 0; r < LC / 8; r++) {
        float p[8];
        #pragma unroll
        for (int j = 0; j < 8; j++) {
            ull xx = sx[r * 8 + j][chl];
            #pragma unroll
            for (int t = 0; t < NPK; t++) h[t] = fma2(a[t], h[t], xx);
            ull acc = mul2(cb[0], h[0]);
            #pragma unroll
            for (int t = 1; t < NPK; t++) acc = fma2(cb[t], h[t], acc);
            p[j] = hsum2(acc);
        }
        // 3-stage register-halving butterfly over the 8-lane team:
        // afterwards lane q holds the finished output for step r*8+q
        #pragma unroll
        for (int d = 4; d >= 1; d >>= 1) {
            #pragma unroll
            for (int m = 0; m < d; m++) {
                bool  hi   = (q & d) != 0;
                float send = hi ? p[m] : p[m + d];
                float got  = __shfl_xor_sync(0xffffffffu, send, d);
                p[m] = (hi ? p[m + d] : p[m]) + got;
            }
        }
        y[(l0 + r * 8 + q) * CH + c] = p[0];
    }
}

// ---------------------------------------------------------------- launch
extern "C" void kernel_launch(void* const* d_in, const int* in_sizes, int n_in,
                              void* d_out, int out_size)
{
    const float* x       = (const float*)d_in[0];
    const float* lognegA = (const float*)d_in[1];
    const float* B       = (const float*)d_in[2];
    const float* C       = (const float*)d_in[3];
    float*       y       = (float*)d_out;

    precompute_k<<<CS / 256, 256>>>(lognegA, B, C);   // also resets flags
    dim3 grid(NC, NG);
    fused_k<<<grid, 256>>>(x, y);
}